// round 15
// baseline (speedup 1.0000x reference)
#include <cuda_runtime.h>
#include <cuda_bf16.h>
#include <cstdint>
#include <cstddef>

#define B_ 64
#define P_ 196
#define ENC_ 2048
#define A_ 512
#define H_ 512
#define E_ 512
#define V_ 30000
#define L_ 30
#define T_ 29
#define NCAT 4608
#define MROW (B_*T_)  // 1856

#define HSPLIT 4
#define GSPLIT 8
#define NBLK 148      // persistent grid: one CTA per SM

// Output layout (float32, concatenated leaves)
#define PREDS_OFF ((size_t)0)
#define CAPS_OFF  ((size_t)B_*T_*V_)
#define DEC_OFF   (CAPS_OFF + (size_t)B_*L_)
#define ALPH_OFF  (DEC_OFF + (size_t)B_)
#define SORT_OFF  (ALPH_OFF + (size_t)B_*T_*P_)

// ---------------- scratch ----------------
__device__ float g_enc_s[(size_t)B_*P_*ENC_];
__device__ uint32_t g_enc_c[(size_t)B_*P_*ENC_];
__device__ float g_att1[(size_t)B_*P_*A_];
__device__ uint32_t g_embc[(size_t)MROW*E_];
__device__ uint32_t g_watt1c[(size_t)A_*ENC_];
__device__ uint32_t g_wembc[(size_t)4*H_*E_];
__device__ uint32_t g_fcwc[(size_t)V_*H_];
__device__ uint32_t g_wcatc[(size_t)NCAT*H_];
__device__ uint32_t g_wawec[(size_t)4*H_*ENC_];
__device__ uint32_t g_hallc[(size_t)(MROW+64)*H_];
__device__ uint32_t g_hc[B_*H_];
__device__ uint32_t g_awec[B_*ENC_];
__device__ float g_embg[(size_t)B_*T_*4*H_];
__device__ float g_wcat[(size_t)NCAT*H_];
__device__ float g_winit[(size_t)2*H_*ENC_];
__device__ float g_initp[4][B_*2*H_];
__device__ float g_houtp[HSPLIT][B_*NCAT];
__device__ float g_h[B_*H_], g_c[B_*H_];
__device__ float g_gates2[GSPLIT][B_*4*H_];
__device__ float g_mean[B_*ENC_];
__device__ float g_bsum[4*H_];
__device__ int   g_sort[B_];
__device__ int   g_dec[B_];
__device__ int   g_cidx[MROW + 64];
__device__ int   g_mact;
__device__ unsigned int g_bar_count;
__device__ unsigned int g_bar_gen;

// ---------------- bf16 hi/lo helpers ----------------
__device__ __forceinline__ void bf16pair(float x0, float x1, uint32_t& hi, uint32_t& lo)
{
    __nv_bfloat16 h0 = __float2bfloat16(x0), h1 = __float2bfloat16(x1);
    float r0 = x0 - __bfloat162float(h0);
    float r1 = x1 - __bfloat162float(h1);
    __nv_bfloat16 l0 = __float2bfloat16(r0), l1 = __float2bfloat16(r1);
    __nv_bfloat162 hh; hh.x = h0; hh.y = h1;
    __nv_bfloat162 ll; ll.x = l0; ll.y = l1;
    hi = *reinterpret_cast<uint32_t*>(&hh);
    lo = *reinterpret_cast<uint32_t*>(&ll);
}

// weight conversion: src [rows][sstride] fp32 -> dst [rows][K u32] hi|lo
__global__ void conv_w(const float* __restrict__ src, int sstride,
                       uint32_t* __restrict__ dst, int rows, int K)
{
    int half = K >> 1;
    long long idx = (long long)blockIdx.x * 256 + threadIdx.x;
    if (idx >= (long long)rows * half) return;
    int n = (int)(idx / half), p = (int)(idx % half);
    float x0 = src[(size_t)n * sstride + 2 * p];
    float x1 = src[(size_t)n * sstride + 2 * p + 1];
    uint32_t hi, lo;
    bf16pair(x0, x1, hi, lo);
    dst[(size_t)n * K + p] = hi;
    dst[(size_t)n * K + half + p] = lo;
}

// ================= tensor-core bf16x3 GEMM =================
#define ASG 1288
#define WSG 2568

__device__ __forceinline__ void mma_bf16(float* d, const uint32_t* a, const uint32_t* b)
{
    asm volatile(
        "mma.sync.aligned.m16n8k16.row.col.f32.bf16.bf16.f32 "
        "{%0,%1,%2,%3}, {%4,%5,%6,%7}, {%8,%9}, {%0,%1,%2,%3};"
        : "+f"(d[0]), "+f"(d[1]), "+f"(d[2]), "+f"(d[3])
        : "r"(a[0]), "r"(a[1]), "r"(a[2]), "r"(a[3]), "r"(b[0]), "r"(b[1]));
}

// k16-group compute: 3 sweeps of 8 independent mmas each (no acc RAW stalls)
__device__ __forceinline__ void mma_group(
    float acc[2][4][4],
    const uint32_t* aB, const uint32_t* wB, int gid, int tq)
{
    uint32_t ah[2][4], al[2][4], bh[4][2], bl[4][2];
#pragma unroll
    for (int mt = 0; mt < 2; mt++) {
        int r0 = (mt * 16 + gid) * 20, r1 = r0 + 160;
        ah[mt][0] = aB[r0 + tq];     ah[mt][1] = aB[r1 + tq];
        ah[mt][2] = aB[r0 + tq + 4]; ah[mt][3] = aB[r1 + tq + 4];
        al[mt][0] = aB[r0 + 8 + tq];     al[mt][1] = aB[r1 + 8 + tq];
        al[mt][2] = aB[r0 + 8 + tq + 4]; al[mt][3] = aB[r1 + 8 + tq + 4];
    }
#pragma unroll
    for (int nt = 0; nt < 4; nt++) {
        int rw = (nt * 8 + gid) * 20;
        bh[nt][0] = wB[rw + tq];     bh[nt][1] = wB[rw + tq + 4];
        bl[nt][0] = wB[rw + 8 + tq]; bl[nt][1] = wB[rw + 8 + tq + 4];
    }
    // sweep 1: ah * bh
#pragma unroll
    for (int nt = 0; nt < 4; nt++)
#pragma unroll
        for (int mt = 0; mt < 2; mt++)
            mma_bf16(acc[mt][nt], ah[mt], bh[nt]);
    // sweep 2: al * bh
#pragma unroll
    for (int nt = 0; nt < 4; nt++)
#pragma unroll
        for (int mt = 0; mt < 2; mt++)
            mma_bf16(acc[mt][nt], al[mt], bh[nt]);
    // sweep 3: ah * bl
#pragma unroll
    for (int nt = 0; nt < 4; nt++)
#pragma unroll
        for (int mt = 0; mt < 2; mt++)
            mma_bf16(acc[mt][nt], ah[mt], bl[nt]);
}

// Core 64x128xKsub bf16x3 GEMM body (256 threads). M fixed = 64 rows.
__device__ __forceinline__ void gemm64_dev(
    const uint32_t* __restrict__ Ac,
    const uint32_t* __restrict__ Wc,
    float* __restrict__ C, int ldc,
    int n0, int Ksub, int kstride, int koffu,
    uint32_t* As, uint32_t* Ws)
{
    int tid = threadIdx.x;
    int lr = tid >> 2, lq = tid & 3;
    int sg = lq >> 1, cofs = (lq & 1) * 4;
    int half = kstride >> 1;

    const uint32_t* Ap = Ac + (size_t)lr * kstride + koffu + lq * 4;
    const uint32_t* Wp0 = Wc + (size_t)(n0 + lr) * kstride + koffu + lq * 4;
    const uint32_t* Wp1 = Wc + (size_t)(n0 + lr + 64) * kstride + koffu + lq * 4;

    uint4 pah = *reinterpret_cast<const uint4*>(Ap);
    uint4 pal = *reinterpret_cast<const uint4*>(Ap + half);
    uint4 pw0h = *reinterpret_cast<const uint4*>(Wp0);
    uint4 pw0l = *reinterpret_cast<const uint4*>(Wp0 + half);
    uint4 pw1h = *reinterpret_cast<const uint4*>(Wp1);
    uint4 pw1l = *reinterpret_cast<const uint4*>(Wp1 + half);

    float acc[2][4][4];
#pragma unroll
    for (int i = 0; i < 2; i++)
#pragma unroll
        for (int j = 0; j < 4; j++)
#pragma unroll
            for (int q = 0; q < 4; q++) acc[i][j][q] = 0.f;

    int lane = tid & 31, wid = tid >> 5;
    int wm = (wid & 1) * 32, wn = (wid >> 1) * 32;
    int gid = lane >> 2, tq = lane & 3;

    for (int k0 = 0;; k0 += 32) {
        *reinterpret_cast<uint4*>(&As[sg * ASG + lr * 20 + cofs])        = pah;
        *reinterpret_cast<uint4*>(&As[sg * ASG + lr * 20 + 8 + cofs])    = pal;
        *reinterpret_cast<uint4*>(&Ws[sg * WSG + lr * 20 + cofs])        = pw0h;
        *reinterpret_cast<uint4*>(&Ws[sg * WSG + lr * 20 + 8 + cofs])    = pw0l;
        *reinterpret_cast<uint4*>(&Ws[sg * WSG + (lr + 64) * 20 + cofs])     = pw1h;
        *reinterpret_cast<uint4*>(&Ws[sg * WSG + (lr + 64) * 20 + 8 + cofs]) = pw1l;
        __syncthreads();
        bool last = (k0 + 32 >= Ksub);
        if (!last) {
            int o = (k0 >> 1) + 16;
            pah  = *reinterpret_cast<const uint4*>(Ap + o);
            pal  = *reinterpret_cast<const uint4*>(Ap + half + o);
            pw0h = *reinterpret_cast<const uint4*>(Wp0 + o);
            pw0l = *reinterpret_cast<const uint4*>(Wp0 + half + o);
            pw1h = *reinterpret_cast<const uint4*>(Wp1 + o);
            pw1l = *reinterpret_cast<const uint4*>(Wp1 + half + o);
        }
#pragma unroll
        for (int g2 = 0; g2 < 2; g2++)
            mma_group(acc, &As[g2 * ASG + wm * 20], &Ws[g2 * WSG + wn * 20], gid, tq);
        if (last) break;
        __syncthreads();
    }

#pragma unroll
    for (int mt = 0; mt < 2; mt++) {
#pragma unroll
        for (int rh = 0; rh < 2; rh++) {
            int r = wm + mt * 16 + rh * 8 + gid;
#pragma unroll
            for (int nt = 0; nt < 4; nt++) {
                int cc = n0 + wn + nt * 8 + tq * 2;
                C[(size_t)r * ldc + cc]     = acc[mt][nt][rh * 2 + 0];
                C[(size_t)r * ldc + cc + 1] = acc[mt][nt][rh * 2 + 1];
            }
        }
    }
}

// standalone tc GEMM (pre/post: att1, embg, fc)
__global__ __launch_bounds__(256)
void gemm_tc(const uint32_t* __restrict__ Ac,
             const uint32_t* __restrict__ Wc,
             float* __restrict__ C, long long ldc,
             const float* __restrict__ bias,
             int N, int Ksub, int kstride,
             const int* __restrict__ cidx, long long csplit)
{
    int m0 = blockIdx.y * 64;
    if (cidx && m0 >= g_mact) return;
    int n0 = blockIdx.x * 128;
    int z = blockIdx.z;
    int koffu = z * (Ksub >> 1);
    C += (long long)z * csplit;

    __shared__ uint32_t As[2 * ASG];
    __shared__ uint32_t Ws[2 * WSG];

    int tid = threadIdx.x;
    int lr = tid >> 2, lq = tid & 3;
    int sg = lq >> 1, cofs = (lq & 1) * 4;
    int half = kstride >> 1;

    int ar = m0 + lr;
    if (cidx) { int c = cidx[ar]; ar = (c < 0) ? 0 : c; }
    const uint32_t* Ap = Ac + (size_t)ar * kstride + koffu + lq * 4;
    int nr0 = n0 + lr, nr1 = n0 + lr + 64;
    nr0 = (nr0 < N) ? nr0 : 0;
    nr1 = (nr1 < N) ? nr1 : 0;
    const uint32_t* Wp0 = Wc + (size_t)nr0 * kstride + koffu + lq * 4;
    const uint32_t* Wp1 = Wc + (size_t)nr1 * kstride + koffu + lq * 4;

    uint4 pah = *reinterpret_cast<const uint4*>(Ap);
    uint4 pal = *reinterpret_cast<const uint4*>(Ap + half);
    uint4 pw0h = *reinterpret_cast<const uint4*>(Wp0);
    uint4 pw0l = *reinterpret_cast<const uint4*>(Wp0 + half);
    uint4 pw1h = *reinterpret_cast<const uint4*>(Wp1);
    uint4 pw1l = *reinterpret_cast<const uint4*>(Wp1 + half);

    float acc[2][4][4];
#pragma unroll
    for (int i = 0; i < 2; i++)
#pragma unroll
        for (int j = 0; j < 4; j++)
#pragma unroll
            for (int q = 0; q < 4; q++) acc[i][j][q] = 0.f;

    int lane = tid & 31, wid = tid >> 5;
    int wm = (wid & 1) * 32, wn = (wid >> 1) * 32;
    int gid = lane >> 2, tq = lane & 3;

    for (int k0 = 0;; k0 += 32) {
        *reinterpret_cast<uint4*>(&As[sg * ASG + lr * 20 + cofs])        = pah;
        *reinterpret_cast<uint4*>(&As[sg * ASG + lr * 20 + 8 + cofs])    = pal;
        *reinterpret_cast<uint4*>(&Ws[sg * WSG + lr * 20 + cofs])        = pw0h;
        *reinterpret_cast<uint4*>(&Ws[sg * WSG + lr * 20 + 8 + cofs])    = pw0l;
        *reinterpret_cast<uint4*>(&Ws[sg * WSG + (lr + 64) * 20 + cofs])     = pw1h;
        *reinterpret_cast<uint4*>(&Ws[sg * WSG + (lr + 64) * 20 + 8 + cofs]) = pw1l;
        __syncthreads();
        bool last = (k0 + 32 >= Ksub);
        if (!last) {
            int o = (k0 >> 1) + 16;
            pah  = *reinterpret_cast<const uint4*>(Ap + o);
            pal  = *reinterpret_cast<const uint4*>(Ap + half + o);
            pw0h = *reinterpret_cast<const uint4*>(Wp0 + o);
            pw0l = *reinterpret_cast<const uint4*>(Wp0 + half + o);
            pw1h = *reinterpret_cast<const uint4*>(Wp1 + o);
            pw1l = *reinterpret_cast<const uint4*>(Wp1 + half + o);
        }
#pragma unroll
        for (int g2 = 0; g2 < 2; g2++)
            mma_group(acc, &As[g2 * ASG + wm * 20], &Ws[g2 * WSG + wn * 20], gid, tq);
        if (last) break;
        __syncthreads();
    }

#pragma unroll
    for (int mt = 0; mt < 2; mt++) {
#pragma unroll
        for (int rh = 0; rh < 2; rh++) {
            int r = m0 + wm + mt * 16 + rh * 8 + gid;
            long long crow = r;
            if (cidx) { int c = cidx[r]; if (c < 0) continue; crow = c; }
#pragma unroll
            for (int nt = 0; nt < 4; nt++) {
                int cc = n0 + wn + nt * 8 + tq * 2;
                float v0 = acc[mt][nt][rh * 2 + 0];
                float v1 = acc[mt][nt][rh * 2 + 1];
                if (cc < N)     C[crow * ldc + cc]     = v0 + (bias ? bias[cc] : 0.f);
                if (cc + 1 < N) C[crow * ldc + cc + 1] = v1 + (bias ? bias[cc + 1] : 0.f);
            }
        }
    }
}

// ---------------- small SIMT GEMM (init only) ----------------
__global__ __launch_bounds__(256)
void gemm_small(const float* __restrict__ A, int lda,
                const float* __restrict__ W, int ldw,
                float* __restrict__ C, long long ldc,
                const float* __restrict__ bias,
                int N, int K,
                long long csplit)
{
    int m0 = blockIdx.y * 32;
    int n0 = blockIdx.x * 128;
    int z = blockIdx.z;
    A += (size_t)z * K;
    W += (size_t)z * K;
    C += (size_t)z * csplit;

    __shared__ float As[32][36];
    __shared__ float Ws[32][132];

    int tid = threadIdx.x;
    int ty = tid >> 5;
    int tx = tid & 31;
    int lr = tid >> 3;
    int lc = (tid & 7) * 4;

    const float* Aptr = A + (size_t)(m0 + lr) * lda + lc;

    float4 aref = *reinterpret_cast<const float4*>(Aptr);
    float4 wref[4];
#pragma unroll
    for (int rr = 0; rr < 4; rr++) {
        int n = n0 + lr + rr * 32;
        wref[rr] = (n < N) ? *reinterpret_cast<const float4*>(W + (size_t)n * ldw + lc)
                           : make_float4(0.f, 0.f, 0.f, 0.f);
    }

    float acc[4][4];
#pragma unroll
    for (int i = 0; i < 4; i++)
#pragma unroll
        for (int j = 0; j < 4; j++) acc[i][j] = 0.f;

    for (int k0 = 0;; k0 += 32) {
        As[lc + 0][lr] = aref.x; As[lc + 1][lr] = aref.y;
        As[lc + 2][lr] = aref.z; As[lc + 3][lr] = aref.w;
#pragma unroll
        for (int rr = 0; rr < 4; rr++) {
            int nl = lr + rr * 32;
            Ws[lc + 0][nl] = wref[rr].x; Ws[lc + 1][nl] = wref[rr].y;
            Ws[lc + 2][nl] = wref[rr].z; Ws[lc + 3][nl] = wref[rr].w;
        }
        __syncthreads();
        bool last = (k0 + 32 >= K);
        if (!last) {
            aref = *reinterpret_cast<const float4*>(Aptr + k0 + 32);
#pragma unroll
            for (int rr = 0; rr < 4; rr++) {
                int n = n0 + lr + rr * 32;
                wref[rr] = (n < N) ? *reinterpret_cast<const float4*>(W + (size_t)n * ldw + k0 + 32 + lc)
                                   : make_float4(0.f, 0.f, 0.f, 0.f);
            }
        }
#pragma unroll
        for (int kk = 0; kk < 32; kk++) {
            float a[4], b[4];
            *reinterpret_cast<float4*>(a) = *reinterpret_cast<const float4*>(&As[kk][ty * 4]);
            *reinterpret_cast<float4*>(b) = *reinterpret_cast<const float4*>(&Ws[kk][tx * 4]);
#pragma unroll
            for (int i = 0; i < 4; i++)
#pragma unroll
                for (int j = 0; j < 4; j++)
                    acc[i][j] = fmaf(a[i], b[j], acc[i][j]);
        }
        if (last) break;
        __syncthreads();
    }

#pragma unroll
    for (int i = 0; i < 4; i++) {
        int m = m0 + ty * 4 + i;
#pragma unroll
        for (int j = 0; j < 4; j++) {
            int n = n0 + tx * 4 + j;
            if (n >= N) continue;
            float v = acc[i][j];
            if (bias) v += bias[n];
            C[(size_t)m * ldc + n] = v;
        }
    }
}

// ---------------- setup kernels ----------------
__global__ void sort_kernel(const int* __restrict__ cap_len,
                            const int* __restrict__ caps,
                            float* __restrict__ out)
{
    int i = threadIdx.x;
    int li = cap_len[i];
    int r = 0;
    for (int j = 0; j < B_; j++) {
        int lj = cap_len[j];
        if (lj > li || (lj == li && j < i)) r++;
    }
    g_sort[r] = i;
    __syncthreads();
    int src = g_sort[i];
    int dl = cap_len[src] - 1;
    g_dec[i] = dl;
    out[SORT_OFF + i] = (float)src;
    out[DEC_OFF + i]  = (float)dl;
    for (int l = 0; l < L_; l++)
        out[CAPS_OFF + (size_t)i * L_ + l] = (float)caps[src * L_ + l];
    __syncthreads();
    int off = 0;
    for (int j = 0; j < i; j++) off += g_dec[j];
    for (int t = 0; t < dl; t++) g_cidx[off + t] = i * T_ + t;
    if (i == B_ - 1) {
        int tot = off + dl;
        g_mact = tot;
        int pad = (tot + 63) & ~63;
        for (int k = tot; k < pad; k++) g_cidx[k] = -1;
    }
}

__global__ void gather_enc(const float* __restrict__ enc)
{
    int bp = blockIdx.x;
    int b = bp / P_;
    const float* src = enc + ((size_t)g_sort[b] * P_ + (bp % P_)) * ENC_;
    float* dst = g_enc_s + (size_t)bp * ENC_;
    uint32_t* dc = g_enc_c + (size_t)bp * ENC_;
    for (int e = threadIdx.x * 4; e < ENC_; e += blockDim.x * 4) {
        float4 v = *reinterpret_cast<const float4*>(src + e);
        *reinterpret_cast<float4*>(dst + e) = v;
        uint32_t h0, l0, h1, l1;
        bf16pair(v.x, v.y, h0, l0);
        bf16pair(v.z, v.w, h1, l1);
        uint2 hh; hh.x = h0; hh.y = h1;
        uint2 ll; ll.x = l0; ll.y = l1;
        *reinterpret_cast<uint2*>(dc + (e >> 1)) = hh;
        *reinterpret_cast<uint2*>(dc + (ENC_ / 2) + (e >> 1)) = ll;
    }
}

__global__ void gather_emb(const int* __restrict__ caps, const float* __restrict__ embed)
{
    int t = blockIdx.x, b = blockIdx.y;
    int tok = caps[g_sort[b] * L_ + t];
    const float* src = embed + (size_t)tok * E_;
    uint32_t* dc = g_embc + ((size_t)b * T_ + t) * E_;
    for (int e = threadIdx.x * 4; e < E_; e += blockDim.x * 4) {
        float4 v = *reinterpret_cast<const float4*>(src + e);
        uint32_t h0, l0, h1, l1;
        bf16pair(v.x, v.y, h0, l0);
        bf16pair(v.z, v.w, h1, l1);
        uint2 hh; hh.x = h0; hh.y = h1;
        uint2 ll; ll.x = l0; ll.y = l1;
        *reinterpret_cast<uint2*>(dc + (e >> 1)) = hh;
        *reinterpret_cast<uint2*>(dc + (E_ / 2) + (e >> 1)) = ll;
    }
}

__global__ void bsum_kernel(const float* __restrict__ bih, const float* __restrict__ bhh)
{
    int i = blockIdx.x * blockDim.x + threadIdx.x;
    if (i < 4 * H_) g_bsum[i] = bih[i] + bhh[i];
}

__global__ void mean_kernel()
{
    int b = blockIdx.y;
    int e = blockIdx.x * 256 + threadIdx.x;
    const float* p = g_enc_s + (size_t)b * P_ * ENC_ + e;
    float s0 = 0.f, s1 = 0.f, s2 = 0.f, s3 = 0.f;
#pragma unroll
    for (int pp = 0; pp < P_; pp += 4) {
        s0 += p[(size_t)pp * ENC_];
        s1 += p[(size_t)(pp + 1) * ENC_];
        s2 += p[(size_t)(pp + 2) * ENC_];
        s3 += p[(size_t)(pp + 3) * ENC_];
    }
    g_mean[b * ENC_ + e] = ((s0 + s1) + (s2 + s3)) * (1.f / P_);
}

__global__ void combine_init(const float* __restrict__ hb, const float* __restrict__ cb)
{
    int b = blockIdx.x, j = threadIdx.x;
    float h = hb[j], c = cb[j];
#pragma unroll
    for (int s = 0; s < 4; s++) {
        h += g_initp[s][b * 2 * H_ + j];
        c += g_initp[s][b * 2 * H_ + H_ + j];
    }
    g_h[b * H_ + j] = h;
    g_c[b * H_ + j] = c;
    __nv_bfloat16 hbf = __float2bfloat16(h);
    float r = h - __bfloat162float(hbf);
    __nv_bfloat16 lbf = __float2bfloat16(r);
    uint32_t hs = *reinterpret_cast<unsigned short*>(&hbf);
    uint32_t ls = *reinterpret_cast<unsigned short*>(&lbf);
    uint32_t hn = __shfl_down_sync(0xffffffffu, hs, 1);
    uint32_t ln = __shfl_down_sync(0xffffffffu, ls, 1);
    if ((j & 1) == 0) {
        g_hc[b * H_ + (j >> 1)] = hs | (hn << 16);
        g_hc[b * H_ + (H_ >> 1) + (j >> 1)] = ls | (ln << 16);
    }
}

// ================= persistent loop kernel =================
__device__ __forceinline__ void grid_barrier()
{
    __syncthreads();
    if (threadIdx.x == 0) {
        __threadfence();
        unsigned int gen = *(volatile unsigned int*)&g_bar_gen;
        if (atomicAdd(&g_bar_count, 1) == NBLK - 1) {
            g_bar_count = 0;
            __threadfence();
            *(volatile unsigned int*)&g_bar_gen = gen + 1;
        } else {
            while (*(volatile unsigned int*)&g_bar_gen == gen) { }
        }
        __threadfence();
    }
    __syncthreads();
}

__global__ __launch_bounds__(256)
void step_loop(const float* __restrict__ dec_att_b,
               const float* __restrict__ fullw, const float* __restrict__ fullb,
               const float* __restrict__ f_beta_b,
               float* __restrict__ out)
{
    __shared__ __align__(16) uint32_t smem[2 * ASG + 2 * WSG];   // ~30.8 KB
    uint32_t* As = smem;
    uint32_t* Ws = smem + 2 * ASG;
    // phase BC shared layout (aliases smem; phases separated by barriers)
    float* f_a2s = reinterpret_cast<float*>(smem);          // [0,512)   att2
    float* f_ev  = reinterpret_cast<float*>(smem) + 512;    // [512,712) scores
    float* f_al  = reinterpret_cast<float*>(smem) + 712;    // [712,912) alpha
    float* f_red = reinterpret_cast<float*>(smem) + 912;    // [912,929) reductions

    int tid = threadIdx.x;
    int w = tid >> 5, lane = tid & 31;

    for (int t = 0; t < T_; t++) {
        // ---- Phase A: hout partials = hc @ wcatc^T (144 units, 1 round) ----
        for (int u = blockIdx.x; u < 36 * HSPLIT; u += NBLK) {
            int z = u % HSPLIT, nt = u / HSPLIT;
            gemm64_dev(g_hc, g_wcatc, g_houtp[z], NCAT,
                       nt * 128, H_ / HSPLIT, H_, z * (H_ / HSPLIT / 2), As, Ws);
            __syncthreads();
        }
        grid_barrier();

        // ---- Phase BC: scores + softmax + awe (128 units = b x e-half) ----
        for (int u = blockIdx.x; u < B_ * 2; u += NBLK) {
            int b = u >> 1, half = u & 1;
            if (g_dec[b] <= t) continue;
            // att2 + bias into shared (512 floats)
            {
                float v0 = dec_att_b[tid], v1 = dec_att_b[tid + 256];
#pragma unroll
                for (int s = 0; s < HSPLIT; s++) {
                    v0 += g_houtp[s][b * NCAT + tid];
                    v1 += g_houtp[s][b * NCAT + tid + 256];
                }
                f_a2s[tid] = v0; f_a2s[tid + 256] = v1;
            }
            __syncthreads();
            // full scores (8 warps, ~25 rows each, float4 x4 chains)
            for (int p = w; p < P_; p += 8) {
                const float4* a1 = reinterpret_cast<const float4*>(
                    g_att1 + ((size_t)b * P_ + p) * A_);
                const float4* a2v = reinterpret_cast<const float4*>(f_a2s);
                const float4* fwv = reinterpret_cast<const float4*>(fullw);
                float s0 = 0.f, s1 = 0.f, s2 = 0.f, s3 = 0.f;
#pragma unroll
                for (int q = 0; q < 4; q++) {
                    int idx = lane + q * 32;
                    float4 av = a1[idx];
                    float4 bv = a2v[idx];
                    float4 fw = fwv[idx];
                    float v0 = fmaxf(av.x + bv.x, 0.f);
                    float v1 = fmaxf(av.y + bv.y, 0.f);
                    float v2 = fmaxf(av.z + bv.z, 0.f);
                    float v3 = fmaxf(av.w + bv.w, 0.f);
                    float sq = fmaf(v0, fw.x, fmaf(v1, fw.y, fmaf(v2, fw.z, v3 * fw.w)));
                    if (q == 0) s0 = sq; else if (q == 1) s1 = sq;
                    else if (q == 2) s2 = sq; else s3 = sq;
                }
                float s = (s0 + s1) + (s2 + s3);
#pragma unroll
                for (int o = 16; o; o >>= 1) s += __shfl_xor_sync(0xffffffffu, s, o);
                if (lane == 0) f_ev[p] = s + fullb[0];
            }
            __syncthreads();
            // softmax over 196
            float x = (tid < P_) ? f_ev[tid] : -3.0e38f;
            float m = x;
#pragma unroll
            for (int o = 16; o; o >>= 1) m = fmaxf(m, __shfl_xor_sync(0xffffffffu, m, o));
            if (lane == 0) f_red[w] = m;
            __syncthreads();
            if (tid < 8) {
                float mm = f_red[tid];
#pragma unroll
                for (int o = 4; o; o >>= 1) mm = fmaxf(mm, __shfl_xor_sync(0xffu, mm, o));
                if (tid == 0) f_red[8] = mm;
            }
            __syncthreads();
            float mx = f_red[8];
            float e = (tid < P_) ? expf(x - mx) : 0.f;
            float s = e;
#pragma unroll
            for (int o = 16; o; o >>= 1) s += __shfl_xor_sync(0xffffffffu, s, o);
            __syncthreads();
            if (lane == 0) f_red[w] = s;
            __syncthreads();
            if (tid < 8) {
                float ss = f_red[tid];
#pragma unroll
                for (int o = 4; o; o >>= 1) ss += __shfl_xor_sync(0xffu, ss, o);
                if (tid == 0) f_red[8] = ss;
            }
            __syncthreads();
            float inv = 1.f / f_red[8];
            if (tid < P_ + 4) {
                float a = (tid < P_) ? e * inv : 0.f;
                f_al[tid] = a;
                if (half == 0 && tid < P_)
                    out[ALPH_OFF + ((size_t)b * T_ + t) * P_ + tid] = a;
            }
            __syncthreads();
            // awe for this e-half: thread handles 4 consecutive e (float4)
            {
                int e4 = half * (ENC_ / 2) + tid * 4;
                const float4* ep = reinterpret_cast<const float4*>(
                    g_enc_s + (size_t)b * P_ * ENC_ + e4);
                const int rs = ENC_ / 4;
                float4 a0 = make_float4(0.f, 0.f, 0.f, 0.f), a1 = a0, a2 = a0, a3 = a0;
                for (int p = 0; p < P_; p += 4) {
                    float w0 = f_al[p], w1 = f_al[p + 1], w2 = f_al[p + 2], w3 = f_al[p + 3];
                    float4 v0 = ep[(size_t)(p + 0) * rs];
                    float4 v1 = ep[(size_t)(p + 1) * rs];
                    float4 v2 = ep[(size_t)(p + 2) * rs];
                    float4 v3 = ep[(size_t)(p + 3) * rs];
                    a0.x = fmaf(w0, v0.x, a0.x); a0.y = fmaf(w0, v0.y, a0.y);
                    a0.z = fmaf(w0, v0.z, a0.z); a0.w = fmaf(w0, v0.w, a0.w);
                    a1.x = fmaf(w1, v1.x, a1.x); a1.y = fmaf(w1, v1.y, a1.y);
                    a1.z = fmaf(w1, v1.z, a1.z); a1.w = fmaf(w1, v1.w, a1.w);
                    a2.x = fmaf(w2, v2.x, a2.x); a2.y = fmaf(w2, v2.y, a2.y);
                    a2.z = fmaf(w2, v2.z, a2.z); a2.w = fmaf(w2, v2.w, a2.w);
                    a3.x = fmaf(w3, v3.x, a3.x); a3.y = fmaf(w3, v3.y, a3.y);
                    a3.z = fmaf(w3, v3.z, a3.z); a3.w = fmaf(w3, v3.w, a3.w);
                }
                float accx = (a0.x + a1.x) + (a2.x + a3.x);
                float accy = (a0.y + a1.y) + (a2.y + a3.y);
                float accz = (a0.z + a1.z) + (a2.z + a3.z);
                float accw = (a0.w + a1.w) + (a2.w + a3.w);
                float gv0 = f_beta_b[e4],     gv1 = f_beta_b[e4 + 1];
                float gv2 = f_beta_b[e4 + 2], gv3 = f_beta_b[e4 + 3];
#pragma unroll
                for (int s2 = 0; s2 < HSPLIT; s2++) {
                    const float* hp = g_houtp[s2] + b * NCAT + A_ + e4;
                    gv0 += hp[0]; gv1 += hp[1]; gv2 += hp[2]; gv3 += hp[3];
                }
                float aw0 = accx / (1.f + expf(-gv0));
                float aw1 = accy / (1.f + expf(-gv1));
                float aw2 = accz / (1.f + expf(-gv2));
                float aw3 = accw / (1.f + expf(-gv3));
                uint32_t h0, l0, h1, l1;
                bf16pair(aw0, aw1, h0, l0);
                bf16pair(aw2, aw3, h1, l1);
                uint2 hh; hh.x = h0; hh.y = h1;
                uint2 ll; ll.x = l0; ll.y = l1;
                *reinterpret_cast<uint2*>(g_awec + b * ENC_ + (e4 >> 1)) = hh;
                *reinterpret_cast<uint2*>(g_awec + b * ENC_ + (ENC_ >> 1) + (e4 >> 1)) = ll;
            }
            __syncthreads();
        }
        grid_barrier();

        // ---- Phase D: gates2 partials = awec @ wawec^T (128 units, 1 round) ----
        for (int u = blockIdx.x; u < 16 * GSPLIT; u += NBLK) {
            int z = u % GSPLIT, nt = u / GSPLIT;
            gemm64_dev(g_awec, g_wawec, g_gates2[z], 4 * H_,
                       nt * 128, ENC_ / GSPLIT, ENC_, z * (ENC_ / GSPLIT / 2), As, Ws);
            __syncthreads();
        }
        grid_barrier();

        // ---- Phase E: LSTM cell (64 units, 2 j per thread) ----
        for (int u = blockIdx.x; u < B_; u += NBLK) {
            int b = u;
            if (g_dec[b] <= t) continue;
            const float* eg = g_embg + ((size_t)b * T_ + t) * 4 * H_;
            int j0 = tid * 2, j1 = j0 + 1;
            float hv2[2];
#pragma unroll
            for (int jj = 0; jj < 2; jj++) {
                int j = (jj == 0) ? j0 : j1;
                float iv = eg[j]          + g_bsum[j];
                float fv = eg[H_ + j]     + g_bsum[H_ + j];
                float gv = eg[2 * H_ + j] + g_bsum[2 * H_ + j];
                float ov = eg[3 * H_ + j] + g_bsum[3 * H_ + j];
#pragma unroll
                for (int s = 0; s < HSPLIT; s++) {
                    const float* hh = g_houtp[s] + b * NCAT + (A_ + ENC_);
                    iv += hh[j]; fv += hh[H_ + j]; gv += hh[2 * H_ + j]; ov += hh[3 * H_ + j];
                }
#pragma unroll
                for (int s = 0; s < GSPLIT; s++) {
                    const float* gp = g_gates2[s] + b * 4 * H_;
                    iv += gp[j]; fv += gp[H_ + j]; gv += gp[2 * H_ + j]; ov += gp[3 * H_ + j];
                }
                float si = 1.f / (1.f + expf(-iv));
                float sf = 1.f / (1.f + expf(-fv));
                float so = 1.f / (1.f + expf(-ov));
                float tg = tanhf(gv);
                float c = sf * g_c[b * H_ + j] + si * tg;
                g_c[b * H_ + j] = c;
                float h = so * tanhf(c);
                g_h[b * H_ + j] = h;
                hv2[jj] = h;
            }
            uint32_t hi, lo;
            bf16pair(hv2[0], hv2[1], hi, lo);
            size_t row = (size_t)b * T_ + t;
            g_hallc[row * H_ + tid] = hi;
            g_hallc[row * H_ + (H_ >> 1) + tid] = lo;
            g_hc[b * H_ + tid] = hi;
            g_hc[b * H_ + (H_ >> 1) + tid] = lo;
        }
        grid_barrier();
    }
}

// ---------------- host ----------------
static inline void launch_tc(const uint32_t* A, const uint32_t* W,
                             float* C, long long ldc, const float* bias,
                             int M, int N, int Ksub, int kstride,
                             const int* cidx, int splits = 1, long long csplit = 0)
{
    dim3 grid((N + 127) / 128, M / 64, splits);
    gemm_tc<<<grid, 256>>>(A, W, C, ldc, bias, N, Ksub, kstride, cidx, csplit);
}

extern "C" void kernel_launch(void* const* d_in, const int* in_sizes, int n_in,
                              void* d_out, int out_size)
{
    const float* encoder_out = (const float*)d_in[0];
    const float* enc_att_w   = (const float*)d_in[1];
    const float* enc_att_b   = (const float*)d_in[2];
    const float* dec_att_w   = (const float*)d_in[3];
    const float* dec_att_b   = (const float*)d_in[4];
    const float* full_att_w  = (const float*)d_in[5];
    const float* full_att_b  = (const float*)d_in[6];
    const float* embed       = (const float*)d_in[7];
    const float* W_ih        = (const float*)d_in[8];
    const float* W_hh        = (const float*)d_in[9];
    const float* b_ih        = (const float*)d_in[10];
    const float* b_hh        = (const float*)d_in[11];
    const float* init_h_w    = (const float*)d_in[12];
    const float* init_h_b    = (const float*)d_in[13];
    const float* init_c_w    = (const float*)d_in[14];
    const float* init_c_b    = (const float*)d_in[15];
    const float* f_beta_w    = (const float*)d_in[16];
    const float* f_beta_b    = (const float*)d_in[17];
    const float* fc_w        = (const float*)d_in[18];
    const float* fc_b        = (const float*)d_in[19];
    const int*   enc_caps    = (const int*)d_in[20];
    const int*   cap_len     = (const int*)d_in[21];
    float* out = (float*)d_out;

    float *p_att1, *p_embg, *p_wcat, *p_winit, *p_initp, *p_mean;
    uint32_t *p_encc, *p_embc, *p_watt1c, *p_wembc, *p_fcwc, *p_hallc,
             *p_wcatc, *p_wawec;
    int *p_cidx;
    cudaGetSymbolAddress((void**)&p_att1,   g_att1);
    cudaGetSymbolAddress((void**)&p_embg,   g_embg);
    cudaGetSymbolAddress((void**)&p_wcat,   g_wcat);
    cudaGetSymbolAddress((void**)&p_winit,  g_winit);
    cudaGetSymbolAddress((void**)&p_initp,  g_initp);
    cudaGetSymbolAddress((void**)&p_mean,   g_mean);
    cudaGetSymbolAddress((void**)&p_encc,   g_enc_c);
    cudaGetSymbolAddress((void**)&p_embc,   g_embc);
    cudaGetSymbolAddress((void**)&p_watt1c, g_watt1c);
    cudaGetSymbolAddress((void**)&p_wembc,  g_wembc);
    cudaGetSymbolAddress((void**)&p_fcwc,   g_fcwc);
    cudaGetSymbolAddress((void**)&p_hallc,  g_hallc);
    cudaGetSymbolAddress((void**)&p_wcatc,  g_wcatc);
    cudaGetSymbolAddress((void**)&p_wawec,  g_wawec);
    cudaGetSymbolAddress((void**)&p_cidx,   g_cidx);

    cudaMemsetAsync(d_out, 0, (size_t)out_size * sizeof(float), 0);

    cudaMemcpyAsync(p_wcat,                            dec_att_w, (size_t)A_ * H_ * 4,     cudaMemcpyDeviceToDevice, 0);
    cudaMemcpyAsync(p_wcat + (size_t)A_ * H_,          f_beta_w,  (size_t)ENC_ * H_ * 4,   cudaMemcpyDeviceToDevice, 0);
    cudaMemcpyAsync(p_wcat + (size_t)(A_ + ENC_) * H_, W_hh,      (size_t)4 * H_ * H_ * 4, cudaMemcpyDeviceToDevice, 0);
    cudaMemcpyAsync(p_winit,                           init_h_w,  (size_t)H_ * ENC_ * 4,   cudaMemcpyDeviceToDevice, 0);
    cudaMemcpyAsync(p_winit + (size_t)H_ * ENC_,       init_c_w,  (size_t)H_ * ENC_ * 4,   cudaMemcpyDeviceToDevice, 0);

    // idx 3 (ncu-profiled) = att1 tc GEMM
    conv_w<<<(A_ * (ENC_ / 2) + 255) / 256, 256>>>(enc_att_w, ENC_, p_watt1c, A_, ENC_);   // 0
    sort_kernel<<<1, B_>>>(cap_len, enc_caps, out);                                        // 1
    gather_enc<<<B_ * P_, 256>>>(encoder_out);                                             // 2
    launch_tc(p_encc, p_watt1c, p_att1, A_, enc_att_b, B_ * P_, A_, ENC_, ENC_, nullptr);  // 3
    gather_emb<<<dim3(T_, B_), 128>>>(enc_caps, embed);
    conv_w<<<(4 * H_ * (E_ / 2) + 255) / 256, 256>>>(W_ih, E_ + ENC_, p_wembc, 4 * H_, E_);
    launch_tc(p_embc, p_wembc, p_embg, 4 * H_, nullptr, MROW, 4 * H_, E_, E_, nullptr);
    conv_w<<<(int)(((size_t)V_ * (H_ / 2) + 255) / 256), 256>>>(fc_w, H_, p_fcwc, V_, H_);
    conv_w<<<(NCAT * (H_ / 2) + 255) / 256, 256>>>(p_wcat, H_, p_wcatc, NCAT, H_);
    conv_w<<<(4 * H_ * (ENC_ / 2) + 255) / 256, 256>>>(W_ih + E_, E_ + ENC_, p_wawec, 4 * H_, ENC_);
    bsum_kernel<<<(4 * H_ + 255) / 256, 256>>>(b_ih, b_hh);
    mean_kernel<<<dim3(ENC_ / 256, B_), 256>>>();
    {
        dim3 grid((2 * H_ + 127) / 128, B_ / 32, 4);
        gemm_small<<<grid, 256>>>(p_mean, ENC_, p_winit, ENC_, p_initp, 2 * H_, nullptr,
                                  2 * H_, ENC_ / 4, (long long)B_ * 2 * H_);
    }
    combine_init<<<B_, H_>>>(init_h_b, init_c_b);

    // the entire recurrent loop in ONE persistent kernel (R10 config)
    step_loop<<<NBLK, 256>>>(dec_att_b, full_att_w, full_att_b, f_beta_b, out);

    // all preds: compacted active rows of hallc @ fcwc^T + fc_b
    launch_tc(p_hallc, p_fcwc, out + PREDS_OFF, V_, fc_b, MROW + 64, V_, H_, H_, p_cidx);
}

// round 16
// speedup vs baseline: 1.0625x; 1.0625x over previous
#include <cuda_runtime.h>
#include <cuda_bf16.h>
#include <cstdint>
#include <cstddef>

#define B_ 64
#define P_ 196
#define ENC_ 2048
#define A_ 512
#define H_ 512
#define E_ 512
#define V_ 30000
#define L_ 30
#define T_ 29
#define NCAT 4608
#define MROW (B_*T_)  // 1856

#define HSPLIT 4
#define GSPLIT 8
#define NBLK 148      // persistent grid: one CTA per SM

// Output layout (float32, concatenated leaves)
#define PREDS_OFF ((size_t)0)
#define CAPS_OFF  ((size_t)B_*T_*V_)
#define DEC_OFF   (CAPS_OFF + (size_t)B_*L_)
#define ALPH_OFF  (DEC_OFF + (size_t)B_)
#define SORT_OFF  (ALPH_OFF + (size_t)B_*T_*P_)

// ---------------- scratch ----------------
__device__ float g_enc_s[(size_t)B_*P_*ENC_];
__device__ uint32_t g_enc_c[(size_t)B_*P_*ENC_];
__device__ float g_att1[(size_t)B_*P_*A_];
__device__ uint32_t g_embc[(size_t)MROW*E_];
__device__ uint32_t g_watt1c[(size_t)A_*ENC_];
__device__ uint32_t g_wembc[(size_t)4*H_*E_];
__device__ uint32_t g_fcwc[(size_t)V_*H_];
__device__ uint32_t g_wcatc[(size_t)NCAT*H_];
__device__ uint32_t g_wawec[(size_t)4*H_*ENC_];
__device__ uint32_t g_hallc[(size_t)(MROW+64)*H_];
__device__ uint32_t g_hc[B_*H_];
__device__ uint32_t g_awec[B_*ENC_];
__device__ float g_embg[(size_t)B_*T_*4*H_];
__device__ float g_wcat[(size_t)NCAT*H_];
__device__ float g_winit[(size_t)2*H_*ENC_];
__device__ float g_initp[4][B_*2*H_];
__device__ float g_houtp[HSPLIT][B_*NCAT];
__device__ float g_h[B_*H_], g_c[B_*H_];
__device__ float g_gates2[GSPLIT][B_*4*H_];
__device__ float g_mean[B_*ENC_];
__device__ float g_bsum[4*H_];
__device__ int   g_sort[B_];
__device__ int   g_dec[B_];
__device__ int   g_cidx[MROW + 64];
__device__ int   g_mact;
__device__ unsigned int g_bar_count;
__device__ unsigned int g_bar_gen;

// ---------------- bf16 hi/lo helpers ----------------
__device__ __forceinline__ void bf16pair(float x0, float x1, uint32_t& hi, uint32_t& lo)
{
    __nv_bfloat16 h0 = __float2bfloat16(x0), h1 = __float2bfloat16(x1);
    float r0 = x0 - __bfloat162float(h0);
    float r1 = x1 - __bfloat162float(h1);
    __nv_bfloat16 l0 = __float2bfloat16(r0), l1 = __float2bfloat16(r1);
    __nv_bfloat162 hh; hh.x = h0; hh.y = h1;
    __nv_bfloat162 ll; ll.x = l0; ll.y = l1;
    hi = *reinterpret_cast<uint32_t*>(&hh);
    lo = *reinterpret_cast<uint32_t*>(&ll);
}

// weight conversion: src [rows][sstride] fp32 -> dst [rows][K u32] hi|lo
__global__ void conv_w(const float* __restrict__ src, int sstride,
                       uint32_t* __restrict__ dst, int rows, int K)
{
    int half = K >> 1;
    long long idx = (long long)blockIdx.x * 256 + threadIdx.x;
    if (idx >= (long long)rows * half) return;
    int n = (int)(idx / half), p = (int)(idx % half);
    float x0 = src[(size_t)n * sstride + 2 * p];
    float x1 = src[(size_t)n * sstride + 2 * p + 1];
    uint32_t hi, lo;
    bf16pair(x0, x1, hi, lo);
    dst[(size_t)n * K + p] = hi;
    dst[(size_t)n * K + half + p] = lo;
}

// ================= tensor-core bf16x3 GEMM =================
#define ASG 1288
#define WSG 2568

__device__ __forceinline__ void mma_bf16(float* d, const uint32_t* a, const uint32_t* b)
{
    asm volatile(
        "mma.sync.aligned.m16n8k16.row.col.f32.bf16.bf16.f32 "
        "{%0,%1,%2,%3}, {%4,%5,%6,%7}, {%8,%9}, {%0,%1,%2,%3};"
        : "+f"(d[0]), "+f"(d[1]), "+f"(d[2]), "+f"(d[3])
        : "r"(a[0]), "r"(a[1]), "r"(a[2]), "r"(a[3]), "r"(b[0]), "r"(b[1]));
}

// Core 64x128xKsub bf16x3 GEMM body (256 threads). M fixed = 64 rows.
__device__ __forceinline__ void gemm64_dev(
    const uint32_t* __restrict__ Ac,
    const uint32_t* __restrict__ Wc,
    float* __restrict__ C, int ldc,
    int n0, int Ksub, int kstride, int koffu,
    uint32_t* As, uint32_t* Ws)
{
    int tid = threadIdx.x;
    int lr = tid >> 2, lq = tid & 3;
    int sg = lq >> 1, cofs = (lq & 1) * 4;
    int half = kstride >> 1;

    const uint32_t* Ap = Ac + (size_t)lr * kstride + koffu + lq * 4;
    const uint32_t* Wp0 = Wc + (size_t)(n0 + lr) * kstride + koffu + lq * 4;
    const uint32_t* Wp1 = Wc + (size_t)(n0 + lr + 64) * kstride + koffu + lq * 4;

    uint4 pah = *reinterpret_cast<const uint4*>(Ap);
    uint4 pal = *reinterpret_cast<const uint4*>(Ap + half);
    uint4 pw0h = *reinterpret_cast<const uint4*>(Wp0);
    uint4 pw0l = *reinterpret_cast<const uint4*>(Wp0 + half);
    uint4 pw1h = *reinterpret_cast<const uint4*>(Wp1);
    uint4 pw1l = *reinterpret_cast<const uint4*>(Wp1 + half);

    float acc[2][4][4];
#pragma unroll
    for (int i = 0; i < 2; i++)
#pragma unroll
        for (int j = 0; j < 4; j++)
#pragma unroll
            for (int q = 0; q < 4; q++) acc[i][j][q] = 0.f;

    int lane = tid & 31, wid = tid >> 5;
    int wm = (wid & 1) * 32, wn = (wid >> 1) * 32;
    int gid = lane >> 2, tq = lane & 3;

    for (int k0 = 0;; k0 += 32) {
        *reinterpret_cast<uint4*>(&As[sg * ASG + lr * 20 + cofs])        = pah;
        *reinterpret_cast<uint4*>(&As[sg * ASG + lr * 20 + 8 + cofs])    = pal;
        *reinterpret_cast<uint4*>(&Ws[sg * WSG + lr * 20 + cofs])        = pw0h;
        *reinterpret_cast<uint4*>(&Ws[sg * WSG + lr * 20 + 8 + cofs])    = pw0l;
        *reinterpret_cast<uint4*>(&Ws[sg * WSG + (lr + 64) * 20 + cofs])     = pw1h;
        *reinterpret_cast<uint4*>(&Ws[sg * WSG + (lr + 64) * 20 + 8 + cofs]) = pw1l;
        __syncthreads();
        bool last = (k0 + 32 >= Ksub);
        if (!last) {
            int o = (k0 >> 1) + 16;
            pah  = *reinterpret_cast<const uint4*>(Ap + o);
            pal  = *reinterpret_cast<const uint4*>(Ap + half + o);
            pw0h = *reinterpret_cast<const uint4*>(Wp0 + o);
            pw0l = *reinterpret_cast<const uint4*>(Wp0 + half + o);
            pw1h = *reinterpret_cast<const uint4*>(Wp1 + o);
            pw1l = *reinterpret_cast<const uint4*>(Wp1 + half + o);
        }
#pragma unroll
        for (int g2 = 0; g2 < 2; g2++) {
            const uint32_t* aB = &As[g2 * ASG + wm * 20];
            const uint32_t* wB = &Ws[g2 * WSG + wn * 20];
            uint32_t ah[2][4], al[2][4];
#pragma unroll
            for (int mt = 0; mt < 2; mt++) {
                int r0 = (mt * 16 + gid) * 20, r1 = r0 + 160;
                ah[mt][0] = aB[r0 + tq];     ah[mt][1] = aB[r1 + tq];
                ah[mt][2] = aB[r0 + tq + 4]; ah[mt][3] = aB[r1 + tq + 4];
                al[mt][0] = aB[r0 + 8 + tq];     al[mt][1] = aB[r1 + 8 + tq];
                al[mt][2] = aB[r0 + 8 + tq + 4]; al[mt][3] = aB[r1 + 8 + tq + 4];
            }
#pragma unroll
            for (int nt = 0; nt < 4; nt++) {
                int rw = (nt * 8 + gid) * 20;
                uint32_t bh[2] = {wB[rw + tq], wB[rw + tq + 4]};
                uint32_t bl[2] = {wB[rw + 8 + tq], wB[rw + 8 + tq + 4]};
#pragma unroll
                for (int mt = 0; mt < 2; mt++) {
                    mma_bf16(acc[mt][nt], ah[mt], bh);
                    mma_bf16(acc[mt][nt], al[mt], bh);
                    mma_bf16(acc[mt][nt], ah[mt], bl);
                }
            }
        }
        if (last) break;
        __syncthreads();
    }

#pragma unroll
    for (int mt = 0; mt < 2; mt++) {
#pragma unroll
        for (int rh = 0; rh < 2; rh++) {
            int r = wm + mt * 16 + rh * 8 + gid;
#pragma unroll
            for (int nt = 0; nt < 4; nt++) {
                int cc = n0 + wn + nt * 8 + tq * 2;
                C[(size_t)r * ldc + cc]     = acc[mt][nt][rh * 2 + 0];
                C[(size_t)r * ldc + cc + 1] = acc[mt][nt][rh * 2 + 1];
            }
        }
    }
}

// standalone tc GEMM (pre/post: att1, embg, fc) — forced 2 CTAs/SM (R13 best)
__global__ __launch_bounds__(256, 2)
void gemm_tc(const uint32_t* __restrict__ Ac,
             const uint32_t* __restrict__ Wc,
             float* __restrict__ C, long long ldc,
             const float* __restrict__ bias,
             int N, int Ksub, int kstride,
             const int* __restrict__ cidx, long long csplit)
{
    int m0 = blockIdx.y * 64;
    if (cidx && m0 >= g_mact) return;
    int n0 = blockIdx.x * 128;
    int z = blockIdx.z;
    int koffu = z * (Ksub >> 1);
    C += (long long)z * csplit;

    __shared__ uint32_t As[2 * ASG];
    __shared__ uint32_t Ws[2 * WSG];

    int tid = threadIdx.x;
    int lr = tid >> 2, lq = tid & 3;
    int sg = lq >> 1, cofs = (lq & 1) * 4;
    int half = kstride >> 1;

    int ar = m0 + lr;
    if (cidx) { int c = cidx[ar]; ar = (c < 0) ? 0 : c; }
    const uint32_t* Ap = Ac + (size_t)ar * kstride + koffu + lq * 4;
    int nr0 = n0 + lr, nr1 = n0 + lr + 64;
    nr0 = (nr0 < N) ? nr0 : 0;
    nr1 = (nr1 < N) ? nr1 : 0;
    const uint32_t* Wp0 = Wc + (size_t)nr0 * kstride + koffu + lq * 4;
    const uint32_t* Wp1 = Wc + (size_t)nr1 * kstride + koffu + lq * 4;

    uint4 pah = *reinterpret_cast<const uint4*>(Ap);
    uint4 pal = *reinterpret_cast<const uint4*>(Ap + half);
    uint4 pw0h = *reinterpret_cast<const uint4*>(Wp0);
    uint4 pw0l = *reinterpret_cast<const uint4*>(Wp0 + half);
    uint4 pw1h = *reinterpret_cast<const uint4*>(Wp1);
    uint4 pw1l = *reinterpret_cast<const uint4*>(Wp1 + half);

    float acc[2][4][4];
#pragma unroll
    for (int i = 0; i < 2; i++)
#pragma unroll
        for (int j = 0; j < 4; j++)
#pragma unroll
            for (int q = 0; q < 4; q++) acc[i][j][q] = 0.f;

    int lane = tid & 31, wid = tid >> 5;
    int wm = (wid & 1) * 32, wn = (wid >> 1) * 32;
    int gid = lane >> 2, tq = lane & 3;

    for (int k0 = 0;; k0 += 32) {
        *reinterpret_cast<uint4*>(&As[sg * ASG + lr * 20 + cofs])        = pah;
        *reinterpret_cast<uint4*>(&As[sg * ASG + lr * 20 + 8 + cofs])    = pal;
        *reinterpret_cast<uint4*>(&Ws[sg * WSG + lr * 20 + cofs])        = pw0h;
        *reinterpret_cast<uint4*>(&Ws[sg * WSG + lr * 20 + 8 + cofs])    = pw0l;
        *reinterpret_cast<uint4*>(&Ws[sg * WSG + (lr + 64) * 20 + cofs])     = pw1h;
        *reinterpret_cast<uint4*>(&Ws[sg * WSG + (lr + 64) * 20 + 8 + cofs]) = pw1l;
        __syncthreads();
        bool last = (k0 + 32 >= Ksub);
        if (!last) {
            int o = (k0 >> 1) + 16;
            pah  = *reinterpret_cast<const uint4*>(Ap + o);
            pal  = *reinterpret_cast<const uint4*>(Ap + half + o);
            pw0h = *reinterpret_cast<const uint4*>(Wp0 + o);
            pw0l = *reinterpret_cast<const uint4*>(Wp0 + half + o);
            pw1h = *reinterpret_cast<const uint4*>(Wp1 + o);
            pw1l = *reinterpret_cast<const uint4*>(Wp1 + half + o);
        }
#pragma unroll
        for (int g2 = 0; g2 < 2; g2++) {
            const uint32_t* aB = &As[g2 * ASG + wm * 20];
            const uint32_t* wB = &Ws[g2 * WSG + wn * 20];
            uint32_t ah[2][4], al[2][4];
#pragma unroll
            for (int mt = 0; mt < 2; mt++) {
                int r0 = (mt * 16 + gid) * 20, r1 = r0 + 160;
                ah[mt][0] = aB[r0 + tq];     ah[mt][1] = aB[r1 + tq];
                ah[mt][2] = aB[r0 + tq + 4]; ah[mt][3] = aB[r1 + tq + 4];
                al[mt][0] = aB[r0 + 8 + tq];     al[mt][1] = aB[r1 + 8 + tq];
                al[mt][2] = aB[r0 + 8 + tq + 4]; al[mt][3] = aB[r1 + 8 + tq + 4];
            }
#pragma unroll
            for (int nt = 0; nt < 4; nt++) {
                int rw = (nt * 8 + gid) * 20;
                uint32_t bh[2] = {wB[rw + tq], wB[rw + tq + 4]};
                uint32_t bl[2] = {wB[rw + 8 + tq], wB[rw + 8 + tq + 4]};
#pragma unroll
                for (int mt = 0; mt < 2; mt++) {
                    mma_bf16(acc[mt][nt], ah[mt], bh);
                    mma_bf16(acc[mt][nt], al[mt], bh);
                    mma_bf16(acc[mt][nt], ah[mt], bl);
                }
            }
        }
        if (last) break;
        __syncthreads();
    }

#pragma unroll
    for (int mt = 0; mt < 2; mt++) {
#pragma unroll
        for (int rh = 0; rh < 2; rh++) {
            int r = m0 + wm + mt * 16 + rh * 8 + gid;
            long long crow = r;
            if (cidx) { int c = cidx[r]; if (c < 0) continue; crow = c; }
#pragma unroll
            for (int nt = 0; nt < 4; nt++) {
                int cc = n0 + wn + nt * 8 + tq * 2;
                float v0 = acc[mt][nt][rh * 2 + 0];
                float v1 = acc[mt][nt][rh * 2 + 1];
                if (cc < N)     C[crow * ldc + cc]     = v0 + (bias ? bias[cc] : 0.f);
                if (cc + 1 < N) C[crow * ldc + cc + 1] = v1 + (bias ? bias[cc + 1] : 0.f);
            }
        }
    }
}

// ---------------- small SIMT GEMM (init only) ----------------
__global__ __launch_bounds__(256)
void gemm_small(const float* __restrict__ A, int lda,
                const float* __restrict__ W, int ldw,
                float* __restrict__ C, long long ldc,
                const float* __restrict__ bias,
                int N, int K,
                long long csplit)
{
    int m0 = blockIdx.y * 32;
    int n0 = blockIdx.x * 128;
    int z = blockIdx.z;
    A += (size_t)z * K;
    W += (size_t)z * K;
    C += (size_t)z * csplit;

    __shared__ float As[32][36];
    __shared__ float Ws[32][132];

    int tid = threadIdx.x;
    int ty = tid >> 5;
    int tx = tid & 31;
    int lr = tid >> 3;
    int lc = (tid & 7) * 4;

    const float* Aptr = A + (size_t)(m0 + lr) * lda + lc;

    float4 aref = *reinterpret_cast<const float4*>(Aptr);
    float4 wref[4];
#pragma unroll
    for (int rr = 0; rr < 4; rr++) {
        int n = n0 + lr + rr * 32;
        wref[rr] = (n < N) ? *reinterpret_cast<const float4*>(W + (size_t)n * ldw + lc)
                           : make_float4(0.f, 0.f, 0.f, 0.f);
    }

    float acc[4][4];
#pragma unroll
    for (int i = 0; i < 4; i++)
#pragma unroll
        for (int j = 0; j < 4; j++) acc[i][j] = 0.f;

    for (int k0 = 0;; k0 += 32) {
        As[lc + 0][lr] = aref.x; As[lc + 1][lr] = aref.y;
        As[lc + 2][lr] = aref.z; As[lc + 3][lr] = aref.w;
#pragma unroll
        for (int rr = 0; rr < 4; rr++) {
            int nl = lr + rr * 32;
            Ws[lc + 0][nl] = wref[rr].x; Ws[lc + 1][nl] = wref[rr].y;
            Ws[lc + 2][nl] = wref[rr].z; Ws[lc + 3][nl] = wref[rr].w;
        }
        __syncthreads();
        bool last = (k0 + 32 >= K);
        if (!last) {
            aref = *reinterpret_cast<const float4*>(Aptr + k0 + 32);
#pragma unroll
            for (int rr = 0; rr < 4; rr++) {
                int n = n0 + lr + rr * 32;
                wref[rr] = (n < N) ? *reinterpret_cast<const float4*>(W + (size_t)n * ldw + k0 + 32 + lc)
                                   : make_float4(0.f, 0.f, 0.f, 0.f);
            }
        }
#pragma unroll
        for (int kk = 0; kk < 32; kk++) {
            float a[4], b[4];
            *reinterpret_cast<float4*>(a) = *reinterpret_cast<const float4*>(&As[kk][ty * 4]);
            *reinterpret_cast<float4*>(b) = *reinterpret_cast<const float4*>(&Ws[kk][tx * 4]);
#pragma unroll
            for (int i = 0; i < 4; i++)
#pragma unroll
                for (int j = 0; j < 4; j++)
                    acc[i][j] = fmaf(a[i], b[j], acc[i][j]);
        }
        if (last) break;
        __syncthreads();
    }

#pragma unroll
    for (int i = 0; i < 4; i++) {
        int m = m0 + ty * 4 + i;
#pragma unroll
        for (int j = 0; j < 4; j++) {
            int n = n0 + tx * 4 + j;
            if (n >= N) continue;
            float v = acc[i][j];
            if (bias) v += bias[n];
            C[(size_t)m * ldc + n] = v;
        }
    }
}

// ---------------- setup kernels ----------------
__global__ void sort_kernel(const int* __restrict__ cap_len,
                            const int* __restrict__ caps,
                            float* __restrict__ out)
{
    int i = threadIdx.x;
    int li = cap_len[i];
    int r = 0;
    for (int j = 0; j < B_; j++) {
        int lj = cap_len[j];
        if (lj > li || (lj == li && j < i)) r++;
    }
    g_sort[r] = i;
    __syncthreads();
    int src = g_sort[i];
    int dl = cap_len[src] - 1;
    g_dec[i] = dl;
    out[SORT_OFF + i] = (float)src;
    out[DEC_OFF + i]  = (float)dl;
    for (int l = 0; l < L_; l++)
        out[CAPS_OFF + (size_t)i * L_ + l] = (float)caps[src * L_ + l];
    __syncthreads();
    int off = 0;
    for (int j = 0; j < i; j++) off += g_dec[j];
    for (int t = 0; t < dl; t++) g_cidx[off + t] = i * T_ + t;
    if (i == B_ - 1) {
        int tot = off + dl;
        g_mact = tot;
        int pad = (tot + 63) & ~63;
        for (int k = tot; k < pad; k++) g_cidx[k] = -1;
    }
}

__global__ void gather_enc(const float* __restrict__ enc)
{
    int bp = blockIdx.x;
    int b = bp / P_;
    const float* src = enc + ((size_t)g_sort[b] * P_ + (bp % P_)) * ENC_;
    float* dst = g_enc_s + (size_t)bp * ENC_;
    uint32_t* dc = g_enc_c + (size_t)bp * ENC_;
    for (int e = threadIdx.x * 4; e < ENC_; e += blockDim.x * 4) {
        float4 v = *reinterpret_cast<const float4*>(src + e);
        *reinterpret_cast<float4*>(dst + e) = v;
        uint32_t h0, l0, h1, l1;
        bf16pair(v.x, v.y, h0, l0);
        bf16pair(v.z, v.w, h1, l1);
        uint2 hh; hh.x = h0; hh.y = h1;
        uint2 ll; ll.x = l0; ll.y = l1;
        *reinterpret_cast<uint2*>(dc + (e >> 1)) = hh;
        *reinterpret_cast<uint2*>(dc + (ENC_ / 2) + (e >> 1)) = ll;
    }
}

__global__ void gather_emb(const int* __restrict__ caps, const float* __restrict__ embed)
{
    int t = blockIdx.x, b = blockIdx.y;
    int tok = caps[g_sort[b] * L_ + t];
    const float* src = embed + (size_t)tok * E_;
    uint32_t* dc = g_embc + ((size_t)b * T_ + t) * E_;
    for (int e = threadIdx.x * 4; e < E_; e += blockDim.x * 4) {
        float4 v = *reinterpret_cast<const float4*>(src + e);
        uint32_t h0, l0, h1, l1;
        bf16pair(v.x, v.y, h0, l0);
        bf16pair(v.z, v.w, h1, l1);
        uint2 hh; hh.x = h0; hh.y = h1;
        uint2 ll; ll.x = l0; ll.y = l1;
        *reinterpret_cast<uint2*>(dc + (e >> 1)) = hh;
        *reinterpret_cast<uint2*>(dc + (E_ / 2) + (e >> 1)) = ll;
    }
}

__global__ void bsum_kernel(const float* __restrict__ bih, const float* __restrict__ bhh)
{
    int i = blockIdx.x * blockDim.x + threadIdx.x;
    if (i < 4 * H_) g_bsum[i] = bih[i] + bhh[i];
}

__global__ void mean_kernel()
{
    int b = blockIdx.y;
    int e = blockIdx.x * 256 + threadIdx.x;
    const float* p = g_enc_s + (size_t)b * P_ * ENC_ + e;
    float s0 = 0.f, s1 = 0.f, s2 = 0.f, s3 = 0.f;
#pragma unroll
    for (int pp = 0; pp < P_; pp += 4) {
        s0 += p[(size_t)pp * ENC_];
        s1 += p[(size_t)(pp + 1) * ENC_];
        s2 += p[(size_t)(pp + 2) * ENC_];
        s3 += p[(size_t)(pp + 3) * ENC_];
    }
    g_mean[b * ENC_ + e] = ((s0 + s1) + (s2 + s3)) * (1.f / P_);
}

__global__ void combine_init(const float* __restrict__ hb, const float* __restrict__ cb)
{
    int b = blockIdx.x, j = threadIdx.x;
    float h = hb[j], c = cb[j];
#pragma unroll
    for (int s = 0; s < 4; s++) {
        h += g_initp[s][b * 2 * H_ + j];
        c += g_initp[s][b * 2 * H_ + H_ + j];
    }
    g_h[b * H_ + j] = h;
    g_c[b * H_ + j] = c;
    __nv_bfloat16 hbf = __float2bfloat16(h);
    float r = h - __bfloat162float(hbf);
    __nv_bfloat16 lbf = __float2bfloat16(r);
    uint32_t hs = *reinterpret_cast<unsigned short*>(&hbf);
    uint32_t ls = *reinterpret_cast<unsigned short*>(&lbf);
    uint32_t hn = __shfl_down_sync(0xffffffffu, hs, 1);
    uint32_t ln = __shfl_down_sync(0xffffffffu, ls, 1);
    if ((j & 1) == 0) {
        g_hc[b * H_ + (j >> 1)] = hs | (hn << 16);
        g_hc[b * H_ + (H_ >> 1) + (j >> 1)] = ls | (ln << 16);
    }
}

// ================= persistent loop kernel =================
__device__ __forceinline__ void grid_barrier()
{
    __syncthreads();
    if (threadIdx.x == 0) {
        __threadfence();
        unsigned int gen = *(volatile unsigned int*)&g_bar_gen;
        if (atomicAdd(&g_bar_count, 1) == NBLK - 1) {
            g_bar_count = 0;
            __threadfence();
            *(volatile unsigned int*)&g_bar_gen = gen + 1;
        } else {
            while (*(volatile unsigned int*)&g_bar_gen == gen) { }
        }
        __threadfence();
    }
    __syncthreads();
}

__global__ __launch_bounds__(256)
void step_loop(const float* __restrict__ dec_att_b,
               const float* __restrict__ fullw, const float* __restrict__ fullb,
               const float* __restrict__ f_beta_b,
               float* __restrict__ out)
{
    __shared__ __align__(16) uint32_t smem[2 * ASG + 2 * WSG];   // ~30.8 KB
    uint32_t* As = smem;
    uint32_t* Ws = smem + 2 * ASG;
    float* f_a2s = reinterpret_cast<float*>(smem);
    float* f_ev  = reinterpret_cast<float*>(smem) + 512;
    float* f_al  = reinterpret_cast<float*>(smem) + 712;
    float* f_red = reinterpret_cast<float*>(smem) + 912;

    int tid = threadIdx.x;
    int w = tid >> 5, lane = tid & 31;

    for (int t = 0; t < T_; t++) {
        // ---- Phase A: hout partials = hc @ wcatc^T (144 units, 1 round) ----
        for (int u = blockIdx.x; u < 36 * HSPLIT; u += NBLK) {
            int z = u % HSPLIT, nt = u / HSPLIT;
            gemm64_dev(g_hc, g_wcatc, g_houtp[z], NCAT,
                       nt * 128, H_ / HSPLIT, H_, z * (H_ / HSPLIT / 2), As, Ws);
            __syncthreads();
        }
        grid_barrier();

        // ---- Phase BC: scores + softmax + awe (128 units = b x e-half) ----
        for (int u = blockIdx.x; u < B_ * 2; u += NBLK) {
            int b = u >> 1, half = u & 1;
            if (g_dec[b] <= t) continue;
            {
                float v0 = dec_att_b[tid], v1 = dec_att_b[tid + 256];
#pragma unroll
                for (int s = 0; s < HSPLIT; s++) {
                    v0 += g_houtp[s][b * NCAT + tid];
                    v1 += g_houtp[s][b * NCAT + tid + 256];
                }
                f_a2s[tid] = v0; f_a2s[tid + 256] = v1;
            }
            __syncthreads();
            for (int p = w; p < P_; p += 8) {
                const float4* a1 = reinterpret_cast<const float4*>(
                    g_att1 + ((size_t)b * P_ + p) * A_);
                const float4* a2v = reinterpret_cast<const float4*>(f_a2s);
                const float4* fwv = reinterpret_cast<const float4*>(fullw);
                float s0 = 0.f, s1 = 0.f, s2 = 0.f, s3 = 0.f;
#pragma unroll
                for (int q = 0; q < 4; q++) {
                    int idx = lane + q * 32;
                    float4 av = a1[idx];
                    float4 bv = a2v[idx];
                    float4 fw = fwv[idx];
                    float v0 = fmaxf(av.x + bv.x, 0.f);
                    float v1 = fmaxf(av.y + bv.y, 0.f);
                    float v2 = fmaxf(av.z + bv.z, 0.f);
                    float v3 = fmaxf(av.w + bv.w, 0.f);
                    float sq = fmaf(v0, fw.x, fmaf(v1, fw.y, fmaf(v2, fw.z, v3 * fw.w)));
                    if (q == 0) s0 = sq; else if (q == 1) s1 = sq;
                    else if (q == 2) s2 = sq; else s3 = sq;
                }
                float s = (s0 + s1) + (s2 + s3);
#pragma unroll
                for (int o = 16; o; o >>= 1) s += __shfl_xor_sync(0xffffffffu, s, o);
                if (lane == 0) f_ev[p] = s + fullb[0];
            }
            __syncthreads();
            float x = (tid < P_) ? f_ev[tid] : -3.0e38f;
            float m = x;
#pragma unroll
            for (int o = 16; o; o >>= 1) m = fmaxf(m, __shfl_xor_sync(0xffffffffu, m, o));
            if (lane == 0) f_red[w] = m;
            __syncthreads();
            if (tid < 8) {
                float mm = f_red[tid];
#pragma unroll
                for (int o = 4; o; o >>= 1) mm = fmaxf(mm, __shfl_xor_sync(0xffu, mm, o));
                if (tid == 0) f_red[8] = mm;
            }
            __syncthreads();
            float mx = f_red[8];
            float e = (tid < P_) ? expf(x - mx) : 0.f;
            float s = e;
#pragma unroll
            for (int o = 16; o; o >>= 1) s += __shfl_xor_sync(0xffffffffu, s, o);
            __syncthreads();
            if (lane == 0) f_red[w] = s;
            __syncthreads();
            if (tid < 8) {
                float ss = f_red[tid];
#pragma unroll
                for (int o = 4; o; o >>= 1) ss += __shfl_xor_sync(0xffu, ss, o);
                if (tid == 0) f_red[8] = ss;
            }
            __syncthreads();
            float inv = 1.f / f_red[8];
            if (tid < P_ + 4) {
                float a = (tid < P_) ? e * inv : 0.f;
                f_al[tid] = a;
                if (half == 0 && tid < P_)
                    out[ALPH_OFF + ((size_t)b * T_ + t) * P_ + tid] = a;
            }
            __syncthreads();
            {
                int e4 = half * (ENC_ / 2) + tid * 4;
                const float4* ep = reinterpret_cast<const float4*>(
                    g_enc_s + (size_t)b * P_ * ENC_ + e4);
                const int rs = ENC_ / 4;
                float4 a0 = make_float4(0.f, 0.f, 0.f, 0.f), a1 = a0, a2 = a0, a3 = a0;
                for (int p = 0; p < P_; p += 4) {
                    float w0 = f_al[p], w1 = f_al[p + 1], w2 = f_al[p + 2], w3 = f_al[p + 3];
                    float4 v0 = ep[(size_t)(p + 0) * rs];
                    float4 v1 = ep[(size_t)(p + 1) * rs];
                    float4 v2 = ep[(size_t)(p + 2) * rs];
                    float4 v3 = ep[(size_t)(p + 3) * rs];
                    a0.x = fmaf(w0, v0.x, a0.x); a0.y = fmaf(w0, v0.y, a0.y);
                    a0.z = fmaf(w0, v0.z, a0.z); a0.w = fmaf(w0, v0.w, a0.w);
                    a1.x = fmaf(w1, v1.x, a1.x); a1.y = fmaf(w1, v1.y, a1.y);
                    a1.z = fmaf(w1, v1.z, a1.z); a1.w = fmaf(w1, v1.w, a1.w);
                    a2.x = fmaf(w2, v2.x, a2.x); a2.y = fmaf(w2, v2.y, a2.y);
                    a2.z = fmaf(w2, v2.z, a2.z); a2.w = fmaf(w2, v2.w, a2.w);
                    a3.x = fmaf(w3, v3.x, a3.x); a3.y = fmaf(w3, v3.y, a3.y);
                    a3.z = fmaf(w3, v3.z, a3.z); a3.w = fmaf(w3, v3.w, a3.w);
                }
                float accx = (a0.x + a1.x) + (a2.x + a3.x);
                float accy = (a0.y + a1.y) + (a2.y + a3.y);
                float accz = (a0.z + a1.z) + (a2.z + a3.z);
                float accw = (a0.w + a1.w) + (a2.w + a3.w);
                float gv0 = f_beta_b[e4],     gv1 = f_beta_b[e4 + 1];
                float gv2 = f_beta_b[e4 + 2], gv3 = f_beta_b[e4 + 3];
#pragma unroll
                for (int s2 = 0; s2 < HSPLIT; s2++) {
                    const float* hp = g_houtp[s2] + b * NCAT + A_ + e4;
                    gv0 += hp[0]; gv1 += hp[1]; gv2 += hp[2]; gv3 += hp[3];
                }
                float aw0 = accx / (1.f + expf(-gv0));
                float aw1 = accy / (1.f + expf(-gv1));
                float aw2 = accz / (1.f + expf(-gv2));
                float aw3 = accw / (1.f + expf(-gv3));
                uint32_t h0, l0, h1, l1;
                bf16pair(aw0, aw1, h0, l0);
                bf16pair(aw2, aw3, h1, l1);
                uint2 hh; hh.x = h0; hh.y = h1;
                uint2 ll; ll.x = l0; ll.y = l1;
                *reinterpret_cast<uint2*>(g_awec + b * ENC_ + (e4 >> 1)) = hh;
                *reinterpret_cast<uint2*>(g_awec + b * ENC_ + (ENC_ >> 1) + (e4 >> 1)) = ll;
            }
            __syncthreads();
        }
        grid_barrier();

        // ---- Phase D: gates2 partials = awec @ wawec^T (128 units, 1 round) ----
        for (int u = blockIdx.x; u < 16 * GSPLIT; u += NBLK) {
            int z = u % GSPLIT, nt = u / GSPLIT;
            gemm64_dev(g_awec, g_wawec, g_gates2[z], 4 * H_,
                       nt * 128, ENC_ / GSPLIT, ENC_, z * (ENC_ / GSPLIT / 2), As, Ws);
            __syncthreads();
        }
        grid_barrier();

        // ---- Phase E: LSTM cell (64 units, 2 j per thread) ----
        for (int u = blockIdx.x; u < B_; u += NBLK) {
            int b = u;
            if (g_dec[b] <= t) continue;
            const float* eg = g_embg + ((size_t)b * T_ + t) * 4 * H_;
            int j0 = tid * 2, j1 = j0 + 1;
            float hv2[2];
#pragma unroll
            for (int jj = 0; jj < 2; jj++) {
                int j = (jj == 0) ? j0 : j1;
                float iv = eg[j]          + g_bsum[j];
                float fv = eg[H_ + j]     + g_bsum[H_ + j];
                float gv = eg[2 * H_ + j] + g_bsum[2 * H_ + j];
                float ov = eg[3 * H_ + j] + g_bsum[3 * H_ + j];
#pragma unroll
                for (int s = 0; s < HSPLIT; s++) {
                    const float* hh = g_houtp[s] + b * NCAT + (A_ + ENC_);
                    iv += hh[j]; fv += hh[H_ + j]; gv += hh[2 * H_ + j]; ov += hh[3 * H_ + j];
                }
#pragma unroll
                for (int s = 0; s < GSPLIT; s++) {
                    const float* gp = g_gates2[s] + b * 4 * H_;
                    iv += gp[j]; fv += gp[H_ + j]; gv += gp[2 * H_ + j]; ov += gp[3 * H_ + j];
                }
                float si = 1.f / (1.f + expf(-iv));
                float sf = 1.f / (1.f + expf(-fv));
                float so = 1.f / (1.f + expf(-ov));
                float tg = tanhf(gv);
                float c = sf * g_c[b * H_ + j] + si * tg;
                g_c[b * H_ + j] = c;
                float h = so * tanhf(c);
                g_h[b * H_ + j] = h;
                hv2[jj] = h;
            }
            uint32_t hi, lo;
            bf16pair(hv2[0], hv2[1], hi, lo);
            size_t row = (size_t)b * T_ + t;
            g_hallc[row * H_ + tid] = hi;
            g_hallc[row * H_ + (H_ >> 1) + tid] = lo;
            g_hc[b * H_ + tid] = hi;
            g_hc[b * H_ + (H_ >> 1) + tid] = lo;
        }
        grid_barrier();
    }
}

// ---------------- host ----------------
static inline void launch_tc_s(cudaStream_t st,
                               const uint32_t* A, const uint32_t* W,
                               float* C, long long ldc, const float* bias,
                               int M, int N, int Ksub, int kstride,
                               const int* cidx, int splits = 1, long long csplit = 0)
{
    dim3 grid((N + 127) / 128, M / 64, splits);
    gemm_tc<<<grid, 256, 0, st>>>(A, W, C, ldc, bias, N, Ksub, kstride, cidx, csplit);
}

extern "C" void kernel_launch(void* const* d_in, const int* in_sizes, int n_in,
                              void* d_out, int out_size)
{
    const float* encoder_out = (const float*)d_in[0];
    const float* enc_att_w   = (const float*)d_in[1];
    const float* enc_att_b   = (const float*)d_in[2];
    const float* dec_att_w   = (const float*)d_in[3];
    const float* dec_att_b   = (const float*)d_in[4];
    const float* full_att_w  = (const float*)d_in[5];
    const float* full_att_b  = (const float*)d_in[6];
    const float* embed       = (const float*)d_in[7];
    const float* W_ih        = (const float*)d_in[8];
    const float* W_hh        = (const float*)d_in[9];
    const float* b_ih        = (const float*)d_in[10];
    const float* b_hh        = (const float*)d_in[11];
    const float* init_h_w    = (const float*)d_in[12];
    const float* init_h_b    = (const float*)d_in[13];
    const float* init_c_w    = (const float*)d_in[14];
    const float* init_c_b    = (const float*)d_in[15];
    const float* f_beta_w    = (const float*)d_in[16];
    const float* f_beta_b    = (const float*)d_in[17];
    const float* fc_w        = (const float*)d_in[18];
    const float* fc_b        = (const float*)d_in[19];
    const int*   enc_caps    = (const int*)d_in[20];
    const int*   cap_len     = (const int*)d_in[21];
    float* out = (float*)d_out;

    float *p_att1, *p_embg, *p_wcat, *p_winit, *p_initp, *p_mean;
    uint32_t *p_encc, *p_embc, *p_watt1c, *p_wembc, *p_fcwc, *p_hallc,
             *p_wcatc, *p_wawec;
    int *p_cidx;
    cudaGetSymbolAddress((void**)&p_att1,   g_att1);
    cudaGetSymbolAddress((void**)&p_embg,   g_embg);
    cudaGetSymbolAddress((void**)&p_wcat,   g_wcat);
    cudaGetSymbolAddress((void**)&p_winit,  g_winit);
    cudaGetSymbolAddress((void**)&p_initp,  g_initp);
    cudaGetSymbolAddress((void**)&p_mean,   g_mean);
    cudaGetSymbolAddress((void**)&p_encc,   g_enc_c);
    cudaGetSymbolAddress((void**)&p_embc,   g_embc);
    cudaGetSymbolAddress((void**)&p_watt1c, g_watt1c);
    cudaGetSymbolAddress((void**)&p_wembc,  g_wembc);
    cudaGetSymbolAddress((void**)&p_fcwc,   g_fcwc);
    cudaGetSymbolAddress((void**)&p_hallc,  g_hallc);
    cudaGetSymbolAddress((void**)&p_wcatc,  g_wcatc);
    cudaGetSymbolAddress((void**)&p_wawec,  g_wawec);
    cudaGetSymbolAddress((void**)&p_cidx,   g_cidx);

    // side stream + events (created once, outside graph capture)
    static cudaStream_t s1 = nullptr;
    static cudaEvent_t eFork = nullptr, eJoin = nullptr;
    if (!s1) {
        cudaStreamCreateWithFlags(&s1, cudaStreamNonBlocking);
        cudaEventCreateWithFlags(&eFork, cudaEventDisableTiming);
        cudaEventCreateWithFlags(&eJoin, cudaEventDisableTiming);
    }

    cudaMemsetAsync(d_out, 0, (size_t)out_size * sizeof(float), 0);

    cudaMemcpyAsync(p_wcat,                            dec_att_w, (size_t)A_ * H_ * 4,     cudaMemcpyDeviceToDevice, 0);
    cudaMemcpyAsync(p_wcat + (size_t)A_ * H_,          f_beta_w,  (size_t)ENC_ * H_ * 4,   cudaMemcpyDeviceToDevice, 0);
    cudaMemcpyAsync(p_wcat + (size_t)(A_ + ENC_) * H_, W_hh,      (size_t)4 * H_ * H_ * 4, cudaMemcpyDeviceToDevice, 0);
    cudaMemcpyAsync(p_winit,                           init_h_w,  (size_t)H_ * ENC_ * 4,   cudaMemcpyDeviceToDevice, 0);
    cudaMemcpyAsync(p_winit + (size_t)H_ * ENC_,       init_c_w,  (size_t)H_ * ENC_ * 4,   cudaMemcpyDeviceToDevice, 0);

    // stream 0: sort first (s1 depends on g_sort via gather_emb)
    conv_w<<<(A_ * (ENC_ / 2) + 255) / 256, 256>>>(enc_att_w, ENC_, p_watt1c, A_, ENC_);   // 0
    sort_kernel<<<1, B_>>>(cap_len, enc_caps, out);                                        // 1
    cudaEventRecord(eFork, 0);

    // ---- stream 1: independent conversions + embedding pipeline ----
    cudaStreamWaitEvent(s1, eFork, 0);
    conv_w<<<(int)(((size_t)V_ * (H_ / 2) + 255) / 256), 256, 0, s1>>>(fc_w, H_, p_fcwc, V_, H_);
    conv_w<<<(4 * H_ * (E_ / 2) + 255) / 256, 256, 0, s1>>>(W_ih, E_ + ENC_, p_wembc, 4 * H_, E_);
    conv_w<<<(4 * H_ * (ENC_ / 2) + 255) / 256, 256, 0, s1>>>(W_ih + E_, E_ + ENC_, p_wawec, 4 * H_, ENC_);
    bsum_kernel<<<(4 * H_ + 255) / 256, 256, 0, s1>>>(b_ih, b_hh);
    gather_emb<<<dim3(T_, B_), 128, 0, s1>>>(enc_caps, embed);
    launch_tc_s(s1, p_embc, p_wembc, p_embg, 4 * H_, nullptr, MROW, 4 * H_, E_, E_, nullptr);
    cudaEventRecord(eJoin, s1);

    // ---- stream 0: enc gather -> att1 (ncu launch idx is best-effort now) ----
    gather_enc<<<B_ * P_, 256>>>(encoder_out);
    launch_tc_s(0, p_encc, p_watt1c, p_att1, A_, enc_att_b, B_ * P_, A_, ENC_, ENC_, nullptr);
    conv_w<<<(NCAT * (H_ / 2) + 255) / 256, 256>>>(p_wcat, H_, p_wcatc, NCAT, H_);
    mean_kernel<<<dim3(ENC_ / 256, B_), 256>>>();
    {
        dim3 grid((2 * H_ + 127) / 128, B_ / 32, 4);
        gemm_small<<<grid, 256>>>(p_mean, ENC_, p_winit, ENC_, p_initp, 2 * H_, nullptr,
                                  2 * H_, ENC_ / 4, (long long)B_ * 2 * H_);
    }
    combine_init<<<B_, H_>>>(init_h_b, init_c_b);

    // join side stream before the loop (loop needs wawec, embg, bsum)
    cudaStreamWaitEvent(0, eJoin, 0);

    // the entire recurrent loop in ONE persistent kernel (R10/R13 config)
    step_loop<<<NBLK, 256>>>(dec_att_b, full_att_w, full_att_b, f_beta_b, out);

    // all preds: compacted active rows of hallc @ fcwc^T + fc_b
    launch_tc_s(0, p_hallc, p_fcwc, out + PREDS_OFF, V_, fc_b, MROW + 64, V_, H_, H_, p_cidx);
}